// round 10
// baseline (speedup 1.0000x reference)
#include <cuda_runtime.h>
#include <cuda_bf16.h>
#include <cstdint>
#include <math.h>

#define BATCH 256
#define TLEN  512
#define COUT  320
#define CPAD  320
#define NSUBJ 4
#define EPSBN 1e-5f

// ================= scratch (no allocations allowed) =================
__device__ float g_bufA[(size_t)BATCH * COUT * TLEN];
__device__ float g_bufB[(size_t)BATCH * COUT * TLEN];
__device__ __nv_bfloat16 g_hi[(size_t)BATCH * TLEN * CPAD];  // [b][t][c] hi split
__device__ __nv_bfloat16 g_lo[(size_t)BATCH * TLEN * CPAD];  // [b][t][c] lo split
__device__ __nv_bfloat16 g_wfmt[3 * 6 * 320 * 320];          // [layer][(ko*2+sp)][co][ci]
__device__ float g_part1[8 * BATCH * COUT];                  // [tt][b][co]
__device__ float g_part2[8 * BATCH * COUT];
__device__ float g_scale[NSUBJ * COUT];
__device__ float g_shift[NSUBJ * COUT];

// ================= mma / ldmatrix / cp.async helpers =================
__device__ __forceinline__ uint32_t smem_addr(const void* p) {
    return (uint32_t)__cvta_generic_to_shared(p);
}
__device__ __forceinline__ void ldsm_x4(uint32_t* r, uint32_t addr) {
    asm volatile("ldmatrix.sync.aligned.m8n8.x4.shared.b16 {%0,%1,%2,%3}, [%4];"
                 : "=r"(r[0]), "=r"(r[1]), "=r"(r[2]), "=r"(r[3]) : "r"(addr));
}
__device__ __forceinline__ void ldsm_x2(uint32_t* r, uint32_t addr) {
    asm volatile("ldmatrix.sync.aligned.m8n8.x2.shared.b16 {%0,%1}, [%2];"
                 : "=r"(r[0]), "=r"(r[1]) : "r"(addr));
}
__device__ __forceinline__ void mma16816(float* c, const uint32_t* a, const uint32_t* b) {
    asm volatile("mma.sync.aligned.m16n8k16.row.col.f32.bf16.bf16.f32 "
                 "{%0,%1,%2,%3}, {%4,%5,%6,%7}, {%8,%9}, {%0,%1,%2,%3};"
                 : "+f"(c[0]), "+f"(c[1]), "+f"(c[2]), "+f"(c[3])
                 : "r"(a[0]), "r"(a[1]), "r"(a[2]), "r"(a[3]), "r"(b[0]), "r"(b[1]));
}
__device__ __forceinline__ void cp16(uint32_t dst, const void* src) {
    asm volatile("cp.async.cg.shared.global [%0], [%1], 16;" :: "r"(dst), "l"(src));
}
__device__ __forceinline__ void cp16z(uint32_t dst, const void* src, int sz) {
    asm volatile("cp.async.cg.shared.global [%0], [%1], 16, %2;" :: "r"(dst), "l"(src), "r"(sz));
}
#define CP_COMMIT() asm volatile("cp.async.commit_group;")
#define CP_WAIT(n)  asm volatile("cp.async.wait_group %0;" :: "n"(n))

// swizzled 16B-half selector: conflict-free ldsm for 32B rows
#define SWH(r, h) ((h) ^ ((r) & 1) ^ (((r) >> 2) & 1))

// ================= conv via warp MMA =================
// CTA tile: 128 t x 160 co; 10 warps (2t x 5co); warp tile 64t x 32co.
// A = X^T smem [row=t][16 ci] (tap = +ko rows), B = W smem [co][16 ci].
// 3 products: (Ahi,Whi) + (Ahi,Wlo) + (Alo,Whi). Double-buffered ci chunks.
#define XSLAB   (132 * 32)               // bytes per split slab
#define XSTG    (2 * XSLAB)              // 8448 B per stage (2 splits)
#define WTILE   (160 * 32)               // 5120 B per (ko,sp) tile
#define WSTG    (6 * WTILE)              // 30720 B per stage
#define WBASE   (2 * XSTG)               // 16896
#define CONV_SMEM (WBASE + 2 * WSTG)     // 78336 B

__global__ __launch_bounds__(320, 2)
void conv_mma_kernel(const __nv_bfloat16* __restrict__ xhi,
                     const __nv_bfloat16* __restrict__ xlo,
                     const __nv_bfloat16* __restrict__ wf,
                     const float* __restrict__ bias,
                     const float* __restrict__ resid,
                     float* __restrict__ out,
                     int nch)
{
    extern __shared__ char smem[];
    const uint32_t sb = smem_addr(smem);

    const int tid  = threadIdx.x;
    const int wid  = tid >> 5;
    const int lane = tid & 31;
    const int co_blk = blockIdx.x * 160;
    const int t0     = blockIdx.y * 128;
    const int b      = blockIdx.z;

    const int warp_t0  = (wid / 5) * 64;       // 0 or 64
    const int warp_co0 = (wid % 5) * 32;       // 0..128

    float acc[4][4][4];
    #pragma unroll
    for (int m = 0; m < 4; m++)
        #pragma unroll
        for (int n = 0; n < 4; n++)
            #pragma unroll
            for (int k = 0; k < 4; k++) acc[m][n][k] = 0.f;

    const int a_row = lane & 15, a_h = lane >> 4;
    const int b_row = lane & 7,  b_h = (lane >> 3) & 1;

    auto load_chunk = [&](int ch, int st) {
        const int c0 = ch * 16;
        // X: 2 splits x 130 rows x 2 halves
        for (int idx = tid; idx < 520; idx += 320) {
            const int sp  = idx / 260;
            const int r2  = idx - sp * 260;
            const int row = r2 >> 1, h = r2 & 1;
            const int t   = t0 - 1 + row;
            const int tc  = t < 0 ? 0 : (t > TLEN - 1 ? TLEN - 1 : t);
            const __nv_bfloat16* src = (sp ? xlo : xhi) +
                ((size_t)b * TLEN + tc) * CPAD + c0 + h * 8;
            const uint32_t dst = sb + st * XSTG + sp * XSLAB + row * 32 + SWH(row, h) * 16;
            cp16z(dst, src, (t >= 0 && t < TLEN) ? 16 : 0);
        }
        // W: 6 tiles x 160 co x 2 halves
        for (int idx = tid; idx < 1920; idx += 320) {
            const int tile = idx / 320;
            const int r    = idx - tile * 320;
            const int co   = r >> 1, h = r & 1;
            const __nv_bfloat16* src = wf + ((size_t)tile * 320 + co_blk + co) * 320 + c0 + h * 8;
            const uint32_t dst = sb + WBASE + st * WSTG + tile * WTILE + co * 32 + SWH(co, h) * 16;
            cp16(dst, src);
        }
        CP_COMMIT();
    };

    load_chunk(0, 0);

    for (int ch = 0; ch < nch; ch++) {
        const int st = ch & 1;
        if (ch + 1 < nch) { load_chunk(ch + 1, st ^ 1); CP_WAIT(1); }
        else              { CP_WAIT(0); }
        __syncthreads();

        const uint32_t xhi_b = sb + st * XSTG;
        const uint32_t xlo_b = xhi_b + XSLAB;
        const uint32_t wb    = sb + WBASE + st * WSTG;

        #pragma unroll
        for (int ko = 0; ko < 3; ko++) {
            uint32_t bh[4][2], bl[4][2];
            #pragma unroll
            for (int n = 0; n < 4; n++) {
                const int wr = warp_co0 + n * 8 + b_row;
                const uint32_t woff = (uint32_t)(wr * 32 + SWH(wr, b_h) * 16);
                ldsm_x2(bh[n], wb + (ko * 2 + 0) * WTILE + woff);
                ldsm_x2(bl[n], wb + (ko * 2 + 1) * WTILE + woff);
            }
            uint32_t a[4][4];
            #pragma unroll
            for (int m = 0; m < 4; m++) {
                const int xr = warp_t0 + m * 16 + ko + a_row;
                ldsm_x4(a[m], xhi_b + (uint32_t)(xr * 32 + SWH(xr, a_h) * 16));
            }
            #pragma unroll
            for (int m = 0; m < 4; m++)
                #pragma unroll
                for (int n = 0; n < 4; n++) mma16816(acc[m][n], a[m], bh[n]);
            #pragma unroll
            for (int m = 0; m < 4; m++)
                #pragma unroll
                for (int n = 0; n < 4; n++) mma16816(acc[m][n], a[m], bl[n]);
            #pragma unroll
            for (int m = 0; m < 4; m++) {
                const int xr = warp_t0 + m * 16 + ko + a_row;
                ldsm_x4(a[m], xlo_b + (uint32_t)(xr * 32 + SWH(xr, a_h) * 16));
            }
            #pragma unroll
            for (int m = 0; m < 4; m++)
                #pragma unroll
                for (int n = 0; n < 4; n++) mma16816(acc[m][n], a[m], bh[n]);
        }
        __syncthreads();
    }

    // ---- epilogue: two 64-t halves via smem transpose; fused BN partial stats ----
    float* sO = (float*)smem;                   // [160 co][68 t-half] = 43520 B
    #pragma unroll
    for (int th = 0; th < 2; th++) {
        if ((warp_t0 >> 6) == th) {
            const int t_l = lane >> 2;
            #pragma unroll
            for (int n = 0; n < 4; n++) {
                const int co_l = warp_co0 + n * 8 + ((lane & 3) << 1);
                #pragma unroll
                for (int m = 0; m < 4; m++) {
                    const int t = m * 16 + t_l;
                    sO[co_l * 68 + t]           = acc[m][n][0];
                    sO[(co_l + 1) * 68 + t]     = acc[m][n][1];
                    sO[co_l * 68 + t + 8]       = acc[m][n][2];
                    sO[(co_l + 1) * 68 + t + 8] = acc[m][n][3];
                }
            }
        }
        __syncthreads();

        const int tt = blockIdx.y * 2 + th;
        for (int idx = tid; idx < 160 * 16; idx += 320) {
            const int co = idx >> 4, t4 = idx & 15;
            float4 v = *(const float4*)&sO[co * 68 + t4 * 4];
            const float bv = bias[co_blk + co];
            v.x += bv; v.y += bv; v.z += bv; v.w += bv;
            const size_t adr = ((size_t)b * COUT + co_blk + co) * TLEN + t0 + th * 64 + t4 * 4;
            if (resid) {
                const float4 r = *(const float4*)&resid[adr];
                v.x += r.x; v.y += r.y; v.z += r.z; v.w += r.w;
            }
            *(float4*)&out[adr] = v;
            // per-(co, 64t-half) partial stats, 16-lane tree reduce
            float s = v.x + v.y + v.z + v.w;
            float q = v.x * v.x + v.y * v.y + v.z * v.z + v.w * v.w;
            #pragma unroll
            for (int o = 8; o > 0; o >>= 1) {
                s += __shfl_down_sync(0xffffffffu, s, o, 16);
                q += __shfl_down_sync(0xffffffffu, q, o, 16);
            }
            if ((lane & 15) == 0) {
                const size_t pa = ((size_t)tt * BATCH + b) * COUT + co_blk + co;
                g_part1[pa] = s;
                g_part2[pa] = q;
            }
        }
        __syncthreads();
    }
}

// ================= weight reformat: [(ko*2+sp)][co320][ci320] bf16 =================
__global__ void wfmt_kernel(const float* __restrict__ W, int Cin, int layer)
{
    const int idx = blockIdx.x * blockDim.x + threadIdx.x;
    if (idx >= 6 * 320 * 320) return;
    const int ci = idx % 320;
    const int co = (idx / 320) % 320;
    const int ts = idx / (320 * 320);
    const int ko = ts >> 1, sp = ts & 1;
    float v = 0.f;
    if (ci < Cin) v = W[((size_t)co * Cin + ci) * 3 + ko];
    const __nv_bfloat16 h = __float2bfloat16(v);
    g_wfmt[(size_t)layer * 6 * 320 * 320 + idx] =
        (sp == 0) ? h : __float2bfloat16(v - __bfloat162float(h));
}

// ================= input convert: X fp32 [b][Cin][512] -> hi/lo [b][t][320] =================
__global__ void convert_x_tr_kernel(const float* __restrict__ x, int Cin)
{
    __shared__ __nv_bfloat16 sh[128][33];
    __shared__ __nv_bfloat16 sl[128][33];
    const int tid = threadIdx.x;
    const int b   = blockIdx.y;
    const int c0  = blockIdx.x * 32;

    for (int ts = 0; ts < TLEN; ts += 128) {
        for (int idx = tid; idx < 1024; idx += 256) {
            const int ci = idx >> 5, t4 = idx & 31;
            const int c = c0 + ci;
            float4 v = make_float4(0.f, 0.f, 0.f, 0.f);
            if (c < Cin) v = *(const float4*)&x[((size_t)b * Cin + c) * TLEN + ts + t4 * 4];
            const float f[4] = {v.x, v.y, v.z, v.w};
            #pragma unroll
            for (int j = 0; j < 4; j++) {
                const __nv_bfloat16 h = __float2bfloat16(f[j]);
                sh[t4 * 4 + j][ci] = h;
                sl[t4 * 4 + j][ci] = __float2bfloat16(f[j] - __bfloat162float(h));
            }
        }
        __syncthreads();
        for (int idx = tid; idx < 1024; idx += 256) {
            const int arr = idx >> 9;
            const int rem = idx & 511;
            const int r = rem >> 2, q = rem & 3;
            const __nv_bfloat16* src = arr ? &sl[r][q * 8] : &sh[r][q * 8];
            uint16_t tmp[8];
            #pragma unroll
            for (int j = 0; j < 8; j++) tmp[j] = ((const uint16_t*)src)[j];
            __nv_bfloat16* dst = (arr ? g_lo : g_hi) + ((size_t)b * TLEN + ts + r) * CPAD + c0 + q * 8;
            *(uint4*)dst = *(const uint4*)tmp;
        }
        __syncthreads();
    }
}

// ================= BN stats reduce: deterministic over [tt][b] =================
__global__ void stats_reduce_g(const int* __restrict__ subj,
                               const float* __restrict__ gamma, const float* __restrict__ beta)
{
    const int idx = blockIdx.x * blockDim.x + threadIdx.x;
    if (idx >= NSUBJ * COUT) return;
    const int s = idx / COUT;
    const int c = idx - s * COUT;
    float sum = 0.f, sq = 0.f;
    int nb = 0;
    for (int b = 0; b < BATCH; b++) {
        if (subj[b] == s) {
            nb++;
            #pragma unroll
            for (int tt = 0; tt < 8; tt++) {
                const size_t pa = ((size_t)tt * BATCH + b) * COUT + c;
                sum += g_part1[pa];
                sq  += g_part2[pa];
            }
        }
    }
    const float cnt  = fmaxf((float)nb * (float)TLEN, 1.0f);
    const float mean = sum / cnt;
    const float var  = sq / cnt - mean * mean;
    const float sc   = gamma[idx] * rsqrtf(var + EPSBN);
    g_scale[idx] = sc;
    g_shift[idx] = beta[idx] - mean * sc;
}

// ====== BN apply + exact GELU (in place) + transposed hi/lo emit ======
__device__ __forceinline__ float gelu_exact(float y) {
    return 0.5f * y * (1.0f + erff(y * 0.70710678118654752440f));
}

__global__ void bn_gelu_tr_kernel(float* __restrict__ x, const int* __restrict__ subj, int emit)
{
    __shared__ __nv_bfloat16 sh[128][33];
    __shared__ __nv_bfloat16 sl[128][33];
    const int tid = threadIdx.x;
    const int b   = blockIdx.y;
    const int c0  = blockIdx.x * 32;
    const int s   = subj[b];

    for (int ts = 0; ts < TLEN; ts += 128) {
        for (int idx = tid; idx < 1024; idx += 256) {
            const int ci = idx >> 5, t4 = idx & 31;
            const int c = c0 + ci;
            const float sc = g_scale[s * COUT + c];
            const float sv = g_shift[s * COUT + c];
            float* xp = &x[((size_t)b * COUT + c) * TLEN + ts + t4 * 4];
            float4 v = *(const float4*)xp;
            v.x = gelu_exact(v.x * sc + sv);
            v.y = gelu_exact(v.y * sc + sv);
            v.z = gelu_exact(v.z * sc + sv);
            v.w = gelu_exact(v.w * sc + sv);
            *(float4*)xp = v;
            if (emit) {
                const float f[4] = {v.x, v.y, v.z, v.w};
                #pragma unroll
                for (int j = 0; j < 4; j++) {
                    const __nv_bfloat16 h = __float2bfloat16(f[j]);
                    sh[t4 * 4 + j][ci] = h;
                    sl[t4 * 4 + j][ci] = __float2bfloat16(f[j] - __bfloat162float(h));
                }
            }
        }
        __syncthreads();
        if (emit) {
            for (int idx = tid; idx < 1024; idx += 256) {
                const int arr = idx >> 9;
                const int rem = idx & 511;
                const int r = rem >> 2, q = rem & 3;
                const __nv_bfloat16* src = arr ? &sl[r][q * 8] : &sh[r][q * 8];
                uint16_t tmp[8];
                #pragma unroll
                for (int j = 0; j < 8; j++) tmp[j] = ((const uint16_t*)src)[j];
                __nv_bfloat16* dst = (arr ? g_lo : g_hi) + ((size_t)b * TLEN + ts + r) * CPAD + c0 + q * 8;
                *(uint4*)dst = *(const uint4*)tmp;
            }
        }
        __syncthreads();
    }
}

// ================= launch =================
extern "C" void kernel_launch(void* const* d_in, const int* in_sizes, int n_in,
                              void* d_out, int out_size)
{
    const float* X    = (const float*)d_in[0];
    const int*   subj = (const int*)  d_in[1];
    const float* w0   = (const float*)d_in[2];
    const float* b0   = (const float*)d_in[3];
    const float* w1   = (const float*)d_in[4];
    const float* b1   = (const float*)d_in[5];
    const float* w2   = (const float*)d_in[6];
    const float* b2   = (const float*)d_in[7];
    const float* g0   = (const float*)d_in[8];
    const float* be0  = (const float*)d_in[9];
    const float* g1   = (const float*)d_in[10];
    const float* be1  = (const float*)d_in[11];
    const float* g2   = (const float*)d_in[12];
    const float* be2  = (const float*)d_in[13];
    float* out = (float*)d_out;

    float* bufA; cudaGetSymbolAddress((void**)&bufA, g_bufA);
    float* bufB; cudaGetSymbolAddress((void**)&bufB, g_bufB);
    __nv_bfloat16* xhi; cudaGetSymbolAddress((void**)&xhi, g_hi);
    __nv_bfloat16* xlo; cudaGetSymbolAddress((void**)&xlo, g_lo);
    __nv_bfloat16* wf;  cudaGetSymbolAddress((void**)&wf,  g_wfmt);
    const size_t wstep = (size_t)6 * 320 * 320;

    cudaFuncSetAttribute(conv_mma_kernel,
                         cudaFuncAttributeMaxDynamicSharedMemorySize, CONV_SMEM);

    const dim3 cgrid(2, 4, BATCH);     // 160-co tiles x 128-t tiles x batch
    const dim3 egrid(10, BATCH);
    const int wfmt_n = 6 * 320 * 320;
    const int rgrid = (NSUBJ * COUT + 255) / 256;

    // ---- prologue: weights + input splits ----
    wfmt_kernel<<<(wfmt_n + 255) / 256, 256>>>(w0, 271, 0);
    wfmt_kernel<<<(wfmt_n + 255) / 256, 256>>>(w1, COUT, 1);
    wfmt_kernel<<<(wfmt_n + 255) / 256, 256>>>(w2, COUT, 2);
    convert_x_tr_kernel<<<egrid, 256>>>(X, 271);

    // ---- layer 0 ----
    conv_mma_kernel<<<cgrid, 320, CONV_SMEM>>>(xhi, xlo, wf, b0, nullptr, bufA, 17);
    stats_reduce_g<<<rgrid, 256>>>(subj, g0, be0);
    bn_gelu_tr_kernel<<<egrid, 256>>>(bufA, subj, 1);

    // ---- layer 1 ----
    conv_mma_kernel<<<cgrid, 320, CONV_SMEM>>>(xhi, xlo, wf + wstep, b1, bufA, bufB, 20);
    stats_reduce_g<<<rgrid, 256>>>(subj, g1, be1);
    bn_gelu_tr_kernel<<<egrid, 256>>>(bufB, subj, 1);

    // ---- layer 2 ----
    conv_mma_kernel<<<cgrid, 320, CONV_SMEM>>>(xhi, xlo, wf + 2 * wstep, b2, bufB, out, 20);
    stats_reduce_g<<<rgrid, 256>>>(subj, g2, be2);
    bn_gelu_tr_kernel<<<egrid, 256>>>(out, subj, 0);
}

// round 11
// speedup vs baseline: 1.0018x; 1.0018x over previous
#include <cuda_runtime.h>
#include <cuda_bf16.h>
#include <cstdint>
#include <math.h>

#define BATCH 256
#define TLEN  512
#define COUT  320
#define CPAD  320
#define NSUBJ 4
#define EPSBN 1e-5f

// ================= scratch (no allocations allowed) =================
__device__ float g_bufA[(size_t)BATCH * COUT * TLEN];
__device__ float g_bufB[(size_t)BATCH * COUT * TLEN];
__device__ __nv_bfloat16 g_hi[(size_t)BATCH * TLEN * CPAD];  // [b][t][c] hi split
__device__ __nv_bfloat16 g_lo[(size_t)BATCH * TLEN * CPAD];  // [b][t][c] lo split
__device__ __nv_bfloat16 g_wfmt[3 * 6 * 320 * 320];          // [layer][(ko*2+sp)][co][ci]
__device__ float g_part1[8 * BATCH * COUT];                  // [tt][b][co]
__device__ float g_part2[8 * BATCH * COUT];
__device__ float g_scale[NSUBJ * COUT];
__device__ float g_shift[NSUBJ * COUT];

// ================= mma / ldmatrix / cp.async helpers =================
__device__ __forceinline__ uint32_t smem_addr(const void* p) {
    return (uint32_t)__cvta_generic_to_shared(p);
}
__device__ __forceinline__ void ldsm_x4(uint32_t* r, uint32_t addr) {
    asm volatile("ldmatrix.sync.aligned.m8n8.x4.shared.b16 {%0,%1,%2,%3}, [%4];"
                 : "=r"(r[0]), "=r"(r[1]), "=r"(r[2]), "=r"(r[3]) : "r"(addr));
}
__device__ __forceinline__ void ldsm_x2(uint32_t* r, uint32_t addr) {
    asm volatile("ldmatrix.sync.aligned.m8n8.x2.shared.b16 {%0,%1}, [%2];"
                 : "=r"(r[0]), "=r"(r[1]) : "r"(addr));
}
__device__ __forceinline__ void mma16816(float* c, const uint32_t* a, const uint32_t* b) {
    asm volatile("mma.sync.aligned.m16n8k16.row.col.f32.bf16.bf16.f32 "
                 "{%0,%1,%2,%3}, {%4,%5,%6,%7}, {%8,%9}, {%0,%1,%2,%3};"
                 : "+f"(c[0]), "+f"(c[1]), "+f"(c[2]), "+f"(c[3])
                 : "r"(a[0]), "r"(a[1]), "r"(a[2]), "r"(a[3]), "r"(b[0]), "r"(b[1]));
}
__device__ __forceinline__ void cp16(uint32_t dst, const void* src) {
    asm volatile("cp.async.cg.shared.global [%0], [%1], 16;" :: "r"(dst), "l"(src));
}
__device__ __forceinline__ void cp16z(uint32_t dst, const void* src, int sz) {
    asm volatile("cp.async.cg.shared.global [%0], [%1], 16, %2;" :: "r"(dst), "l"(src), "r"(sz));
}
#define CP_COMMIT() asm volatile("cp.async.commit_group;")
#define CP_WAIT(n)  asm volatile("cp.async.wait_group %0;" :: "n"(n))

// swizzled 16B-half selector: conflict-free for 32B rows
#define SWH(r, h) ((h) ^ ((r) & 1) ^ (((r) >> 2) & 1))

// ================= conv via warp MMA =================
// CTA tile: 256 t x 64 co; 8 warps (4 t-warps x 2 co-warps); warp tile 64t x 32co.
// A = X^T smem [row=t][16 ci] (tap = +ko rows), B = W smem [co][16 ci].
// 3 products: (Ahi,Whi) + (Ahi,Wlo) + (Alo,Whi). Double-buffered ci chunks.
#define XROWS   260                      // 258 used (t0-1 .. t0+256), pad to 260
#define XSLAB   (XROWS * 32)             // bytes per split slab (8320)
#define XSTG    (2 * XSLAB)              // 16640 B per stage
#define WTILE   (64 * 32)                // 2048 B per (ko,sp) tile
#define WSTG    (6 * WTILE)              // 12288 B per stage
#define WBASE   (2 * XSTG)               // 33280
#define CONV_SMEM (WBASE + 2 * WSTG)     // 57856 B

__global__ __launch_bounds__(256, 2)
void conv_mma_kernel(const __nv_bfloat16* __restrict__ xhi,
                     const __nv_bfloat16* __restrict__ xlo,
                     const __nv_bfloat16* __restrict__ wf,
                     const float* __restrict__ bias,
                     const float* __restrict__ resid,
                     float* __restrict__ out,
                     int nch)
{
    extern __shared__ char smem[];
    const uint32_t sb = smem_addr(smem);

    const int tid  = threadIdx.x;
    const int wid  = tid >> 5;
    const int lane = tid & 31;
    const int co_blk = blockIdx.x * 64;
    const int t0     = blockIdx.y * 256;
    const int b      = blockIdx.z;

    const int warp_t0  = (wid >> 1) * 64;      // 0,64,128,192
    const int warp_co0 = (wid & 1) * 32;       // 0,32

    float acc[4][4][4];
    #pragma unroll
    for (int m = 0; m < 4; m++)
        #pragma unroll
        for (int n = 0; n < 4; n++)
            #pragma unroll
            for (int k = 0; k < 4; k++) acc[m][n][k] = 0.f;

    const int a_row = lane & 15, a_h = lane >> 4;
    const int b_row = lane & 7,  b_h = (lane >> 3) & 1;

    auto load_chunk = [&](int ch, int st) {
        const int c0 = ch * 16;
        // X: 2 splits x 258 rows x 2 halves = 1032 cp16
        for (int idx = tid; idx < 1032; idx += 256) {
            const int sp  = idx / 516;
            const int r2  = idx - sp * 516;
            const int row = r2 >> 1, h = r2 & 1;
            const int t   = t0 - 1 + row;
            const int tc  = t < 0 ? 0 : (t > TLEN - 1 ? TLEN - 1 : t);
            const __nv_bfloat16* src = (sp ? xlo : xhi) +
                ((size_t)b * TLEN + tc) * CPAD + c0 + h * 8;
            const uint32_t dst = sb + st * XSTG + sp * XSLAB + row * 32 + SWH(row, h) * 16;
            cp16z(dst, src, (t >= 0 && t < TLEN) ? 16 : 0);
        }
        // W: 6 tiles x 64 co x 2 halves = 768 cp16
        for (int idx = tid; idx < 768; idx += 256) {
            const int tile = idx >> 7;
            const int r    = idx & 127;
            const int co   = r >> 1, h = r & 1;
            const __nv_bfloat16* src = wf + ((size_t)tile * 320 + co_blk + co) * 320 + c0 + h * 8;
            const uint32_t dst = sb + WBASE + st * WSTG + tile * WTILE + co * 32 + SWH(co, h) * 16;
            cp16(dst, src);
        }
        CP_COMMIT();
    };

    load_chunk(0, 0);

    for (int ch = 0; ch < nch; ch++) {
        const int st = ch & 1;
        if (ch + 1 < nch) { load_chunk(ch + 1, st ^ 1); CP_WAIT(1); }
        else              { CP_WAIT(0); }
        __syncthreads();

        const uint32_t xhi_b = sb + st * XSTG;
        const uint32_t xlo_b = xhi_b + XSLAB;
        const uint32_t wb    = sb + WBASE + st * WSTG;

        #pragma unroll
        for (int ko = 0; ko < 3; ko++) {
            uint32_t bh[4][2], bl[4][2];
            #pragma unroll
            for (int n = 0; n < 4; n++) {
                const int wr = warp_co0 + n * 8 + b_row;
                const uint32_t woff = (uint32_t)(wr * 32 + SWH(wr, b_h) * 16);
                ldsm_x2(bh[n], wb + (ko * 2 + 0) * WTILE + woff);
                ldsm_x2(bl[n], wb + (ko * 2 + 1) * WTILE + woff);
            }
            uint32_t a[4][4];
            #pragma unroll
            for (int m = 0; m < 4; m++) {
                const int xr = warp_t0 + m * 16 + ko + a_row;
                ldsm_x4(a[m], xhi_b + (uint32_t)(xr * 32 + SWH(xr, a_h) * 16));
            }
            #pragma unroll
            for (int m = 0; m < 4; m++)
                #pragma unroll
                for (int n = 0; n < 4; n++) mma16816(acc[m][n], a[m], bh[n]);
            #pragma unroll
            for (int m = 0; m < 4; m++)
                #pragma unroll
                for (int n = 0; n < 4; n++) mma16816(acc[m][n], a[m], bl[n]);
            #pragma unroll
            for (int m = 0; m < 4; m++) {
                const int xr = warp_t0 + m * 16 + ko + a_row;
                ldsm_x4(a[m], xlo_b + (uint32_t)(xr * 32 + SWH(xr, a_h) * 16));
            }
            #pragma unroll
            for (int m = 0; m < 4; m++)
                #pragma unroll
                for (int n = 0; n < 4; n++) mma16816(acc[m][n], a[m], bh[n]);
        }
        __syncthreads();
    }

    // ---- epilogue: four 64-t halves via smem transpose; fused BN partial stats ----
    float* sO = (float*)smem;                   // [64 co][68 t-half] = 17408 B
    #pragma unroll
    for (int th = 0; th < 4; th++) {
        if ((warp_t0 >> 6) == th) {
            const int t_l = lane >> 2;
            #pragma unroll
            for (int n = 0; n < 4; n++) {
                const int co_l = warp_co0 + n * 8 + ((lane & 3) << 1);
                #pragma unroll
                for (int m = 0; m < 4; m++) {
                    const int t = m * 16 + t_l;
                    sO[co_l * 68 + t]           = acc[m][n][0];
                    sO[(co_l + 1) * 68 + t]     = acc[m][n][1];
                    sO[co_l * 68 + t + 8]       = acc[m][n][2];
                    sO[(co_l + 1) * 68 + t + 8] = acc[m][n][3];
                }
            }
        }
        __syncthreads();

        const int tt = blockIdx.y * 4 + th;
        for (int idx = tid; idx < 64 * 16; idx += 256) {
            const int co = idx >> 4, t4 = idx & 15;
            float4 v = *(const float4*)&sO[co * 68 + t4 * 4];
            const float bv = bias[co_blk + co];
            v.x += bv; v.y += bv; v.z += bv; v.w += bv;
            const size_t adr = ((size_t)b * COUT + co_blk + co) * TLEN + t0 + th * 64 + t4 * 4;
            if (resid) {
                const float4 r = *(const float4*)&resid[adr];
                v.x += r.x; v.y += r.y; v.z += r.z; v.w += r.w;
            }
            *(float4*)&out[adr] = v;
            // per-(co, 64t-chunk) partial stats via 16-lane tree reduce
            float s = v.x + v.y + v.z + v.w;
            float q = v.x * v.x + v.y * v.y + v.z * v.z + v.w * v.w;
            #pragma unroll
            for (int o = 8; o > 0; o >>= 1) {
                s += __shfl_down_sync(0xffffffffu, s, o, 16);
                q += __shfl_down_sync(0xffffffffu, q, o, 16);
            }
            if ((lane & 15) == 0) {
                const size_t pa = ((size_t)tt * BATCH + b) * COUT + co_blk + co;
                g_part1[pa] = s;
                g_part2[pa] = q;
            }
        }
        __syncthreads();
    }
}

// ================= weight reformat: [(ko*2+sp)][co320][ci320] bf16 =================
__global__ void wfmt_kernel(const float* __restrict__ W, int Cin, int layer)
{
    const int idx = blockIdx.x * blockDim.x + threadIdx.x;
    if (idx >= 6 * 320 * 320) return;
    const int ci = idx % 320;
    const int co = (idx / 320) % 320;
    const int ts = idx / (320 * 320);
    const int ko = ts >> 1, sp = ts & 1;
    float v = 0.f;
    if (ci < Cin) v = W[((size_t)co * Cin + ci) * 3 + ko];
    const __nv_bfloat16 h = __float2bfloat16(v);
    g_wfmt[(size_t)layer * 6 * 320 * 320 + idx] =
        (sp == 0) ? h : __float2bfloat16(v - __bfloat162float(h));
}

// ================= input convert: X fp32 [b][Cin][512] -> hi/lo [b][t][320] =================
__global__ void convert_x_tr_kernel(const float* __restrict__ x, int Cin)
{
    __shared__ __nv_bfloat16 sh[128][33];
    __shared__ __nv_bfloat16 sl[128][33];
    const int tid = threadIdx.x;
    const int b   = blockIdx.y;
    const int c0  = blockIdx.x * 32;

    for (int ts = 0; ts < TLEN; ts += 128) {
        for (int idx = tid; idx < 1024; idx += 256) {
            const int ci = idx >> 5, t4 = idx & 31;
            const int c = c0 + ci;
            float4 v = make_float4(0.f, 0.f, 0.f, 0.f);
            if (c < Cin) v = *(const float4*)&x[((size_t)b * Cin + c) * TLEN + ts + t4 * 4];
            const float f[4] = {v.x, v.y, v.z, v.w};
            #pragma unroll
            for (int j = 0; j < 4; j++) {
                const __nv_bfloat16 h = __float2bfloat16(f[j]);
                sh[t4 * 4 + j][ci] = h;
                sl[t4 * 4 + j][ci] = __float2bfloat16(f[j] - __bfloat162float(h));
            }
        }
        __syncthreads();
        for (int idx = tid; idx < 1024; idx += 256) {
            const int arr = idx >> 9;
            const int rem = idx & 511;
            const int r = rem >> 2, q = rem & 3;
            const __nv_bfloat16* src = arr ? &sl[r][q * 8] : &sh[r][q * 8];
            uint16_t tmp[8];
            #pragma unroll
            for (int j = 0; j < 8; j++) tmp[j] = ((const uint16_t*)src)[j];
            __nv_bfloat16* dst = (arr ? g_lo : g_hi) + ((size_t)b * TLEN + ts + r) * CPAD + c0 + q * 8;
            *(uint4*)dst = *(const uint4*)tmp;
        }
        __syncthreads();
    }
}

// ================= BN stats reduce: deterministic over [tt][b] =================
__global__ void stats_reduce_g(const int* __restrict__ subj,
                               const float* __restrict__ gamma, const float* __restrict__ beta)
{
    const int idx = blockIdx.x * blockDim.x + threadIdx.x;
    if (idx >= NSUBJ * COUT) return;
    const int s = idx / COUT;
    const int c = idx - s * COUT;
    float sum = 0.f, sq = 0.f;
    int nb = 0;
    for (int b = 0; b < BATCH; b++) {
        if (subj[b] == s) {
            nb++;
            #pragma unroll
            for (int tt = 0; tt < 8; tt++) {
                const size_t pa = ((size_t)tt * BATCH + b) * COUT + c;
                sum += g_part1[pa];
                sq  += g_part2[pa];
            }
        }
    }
    const float cnt  = fmaxf((float)nb * (float)TLEN, 1.0f);
    const float mean = sum / cnt;
    const float var  = sq / cnt - mean * mean;
    const float sc   = gamma[idx] * rsqrtf(var + EPSBN);
    g_scale[idx] = sc;
    g_shift[idx] = beta[idx] - mean * sc;
}

// ====== BN apply + exact GELU (in place) + transposed hi/lo emit ======
__device__ __forceinline__ float gelu_exact(float y) {
    return 0.5f * y * (1.0f + erff(y * 0.70710678118654752440f));
}

__global__ void bn_gelu_tr_kernel(float* __restrict__ x, const int* __restrict__ subj, int emit)
{
    __shared__ __nv_bfloat16 sh[128][33];
    __shared__ __nv_bfloat16 sl[128][33];
    const int tid = threadIdx.x;
    const int b   = blockIdx.y;
    const int c0  = blockIdx.x * 32;
    const int s   = subj[b];

    for (int ts = 0; ts < TLEN; ts += 128) {
        for (int idx = tid; idx < 1024; idx += 256) {
            const int ci = idx >> 5, t4 = idx & 31;
            const int c = c0 + ci;
            const float sc = g_scale[s * COUT + c];
            const float sv = g_shift[s * COUT + c];
            float* xp = &x[((size_t)b * COUT + c) * TLEN + ts + t4 * 4];
            float4 v = *(const float4*)xp;
            v.x = gelu_exact(v.x * sc + sv);
            v.y = gelu_exact(v.y * sc + sv);
            v.z = gelu_exact(v.z * sc + sv);
            v.w = gelu_exact(v.w * sc + sv);
            *(float4*)xp = v;
            if (emit) {
                const float f[4] = {v.x, v.y, v.z, v.w};
                #pragma unroll
                for (int j = 0; j < 4; j++) {
                    const __nv_bfloat16 h = __float2bfloat16(f[j]);
                    sh[t4 * 4 + j][ci] = h;
                    sl[t4 * 4 + j][ci] = __float2bfloat16(f[j] - __bfloat162float(h));
                }
            }
        }
        __syncthreads();
        if (emit) {
            for (int idx = tid; idx < 1024; idx += 256) {
                const int arr = idx >> 9;
                const int rem = idx & 511;
                const int r = rem >> 2, q = rem & 3;
                const __nv_bfloat16* src = arr ? &sl[r][q * 8] : &sh[r][q * 8];
                uint16_t tmp[8];
                #pragma unroll
                for (int j = 0; j < 8; j++) tmp[j] = ((const uint16_t*)src)[j];
                __nv_bfloat16* dst = (arr ? g_lo : g_hi) + ((size_t)b * TLEN + ts + r) * CPAD + c0 + q * 8;
                *(uint4*)dst = *(const uint4*)tmp;
            }
        }
        __syncthreads();
    }
}

// ================= launch =================
extern "C" void kernel_launch(void* const* d_in, const int* in_sizes, int n_in,
                              void* d_out, int out_size)
{
    const float* X    = (const float*)d_in[0];
    const int*   subj = (const int*)  d_in[1];
    const float* w0   = (const float*)d_in[2];
    const float* b0   = (const float*)d_in[3];
    const float* w1   = (const float*)d_in[4];
    const float* b1   = (const float*)d_in[5];
    const float* w2   = (const float*)d_in[6];
    const float* b2   = (const float*)d_in[7];
    const float* g0   = (const float*)d_in[8];
    const float* be0  = (const float*)d_in[9];
    const float* g1   = (const float*)d_in[10];
    const float* be1  = (const float*)d_in[11];
    const float* g2   = (const float*)d_in[12];
    const float* be2  = (const float*)d_in[13];
    float* out = (float*)d_out;

    float* bufA; cudaGetSymbolAddress((void**)&bufA, g_bufA);
    float* bufB; cudaGetSymbolAddress((void**)&bufB, g_bufB);
    __nv_bfloat16* xhi; cudaGetSymbolAddress((void**)&xhi, g_hi);
    __nv_bfloat16* xlo; cudaGetSymbolAddress((void**)&xlo, g_lo);
    __nv_bfloat16* wf;  cudaGetSymbolAddress((void**)&wf,  g_wfmt);
    const size_t wstep = (size_t)6 * 320 * 320;

    cudaFuncSetAttribute(conv_mma_kernel,
                         cudaFuncAttributeMaxDynamicSharedMemorySize, CONV_SMEM);

    const dim3 cgrid(5, 2, BATCH);     // 64-co tiles x 256-t tiles x batch
    const dim3 egrid(10, BATCH);
    const int wfmt_n = 6 * 320 * 320;
    const int rgrid = (NSUBJ * COUT + 255) / 256;

    // ---- prologue: weights + input splits ----
    wfmt_kernel<<<(wfmt_n + 255) / 256, 256>>>(w0, 271, 0);
    wfmt_kernel<<<(wfmt_n + 255) / 256, 256>>>(w1, COUT, 1);
    wfmt_kernel<<<(wfmt_n + 255) / 256, 256>>>(w2, COUT, 2);
    convert_x_tr_kernel<<<egrid, 256>>>(X, 271);

    // ---- layer 0 ----
    conv_mma_kernel<<<cgrid, 256, CONV_SMEM>>>(xhi, xlo, wf, b0, nullptr, bufA, 17);
    stats_reduce_g<<<rgrid, 256>>>(subj, g0, be0);
    bn_gelu_tr_kernel<<<egrid, 256>>>(bufA, subj, 1);

    // ---- layer 1 ----
    conv_mma_kernel<<<cgrid, 256, CONV_SMEM>>>(xhi, xlo, wf + wstep, b1, bufA, bufB, 20);
    stats_reduce_g<<<rgrid, 256>>>(subj, g1, be1);
    bn_gelu_tr_kernel<<<egrid, 256>>>(bufB, subj, 1);

    // ---- layer 2 ----
    conv_mma_kernel<<<cgrid, 256, CONV_SMEM>>>(xhi, xlo, wf + 2 * wstep, b2, bufB, out, 20);
    stats_reduce_g<<<rgrid, 256>>>(subj, g2, be2);
    bn_gelu_tr_kernel<<<egrid, 256>>>(out, subj, 0);
}